// round 15
// baseline (speedup 1.0000x reference)
#include <cuda_runtime.h>
#include <math.h>
#include <stdint.h>

#define E_EDGES 128000
#define N_ATOMS 8000
#define LE_EDGES 512000
#define EH 16384000
#define NGRAPH 64
#define PI_D 3.14159265358979323846

static __device__ __align__(256) unsigned char g_scratch[1245000000];

__device__ __forceinline__ float sigf(float x){ return 1.f/(1.f+expf(-x)); }
__device__ __forceinline__ float siluf(float x){ return x*sigf(x); }
__device__ __forceinline__ float silupf(float x){ float s=sigf(x); return s*(1.f+x*(1.f-s)); }

// SGEMM 128x128x8, 256 thr, 8x8/thread, register-prefetch double buffer.
// AMODE:0 plain,1 silu,2 rowscale,3 silu'(A2)
// EPI: 0 P=acc(+bias)  3 P=acc,R=Q+silu(acc)  7 P=acc+bias+silu(Q)
template<int AMODE,int EPI>
__global__ __launch_bounds__(256)
void gemm_k(const float* __restrict__ A, const float* __restrict__ A2,
            const float* __restrict__ rs, const float* __restrict__ B,
            const float* __restrict__ bias, const float* __restrict__ Q,
            float* __restrict__ P, float* __restrict__ R, int M,int N,int K)
{
  __shared__ float As[8][128];
  __shared__ float Bs[8][128];
  int tid=threadIdx.x;
  int tx=tid&15, ty=tid>>4;             // 16x16 thread grid
  int row0=blockIdx.x*128, col0=blockIdx.y*128;
  float acc[8][8];
  #pragma unroll
  for(int i=0;i<8;i++)
    #pragma unroll
    for(int j=0;j<8;j++) acc[i][j]=0.f;
  int arow=tid>>1, ac4=(tid&1)*4;       // A tile: 128 rows x 8 cols
  int brow=tid>>5, bcol=(tid&31)*4;     // B tile: 8 rows x 128 cols
  float rsv=(AMODE==2)?rs[row0+arow]:0.f;
  float aR[4], bR[4];

  auto loadA=[&](int kb){
    #pragma unroll
    for(int i=0;i<4;i++){
      int k=kb+ac4+i; float v=0.f;
      if(k<K){
        size_t ai=(size_t)(row0+arow)*K+k; v=A[ai];
        if(AMODE==1) v=siluf(v); else if(AMODE==2) v*=rsv;
        else if(AMODE==3) v*=silupf(A2[ai]);
      }
      aR[i]=v;
    }
  };
  auto loadB=[&](int kb){
    #pragma unroll
    for(int i=0;i<4;i++){
      int k=kb+brow, c=col0+bcol+i;
      bR[i]=(k<K&&c<N)?B[(size_t)k*N+c]:0.f;
    }
  };
  loadA(0); loadB(0);

  for(int kb=0;kb<K;kb+=8){
    #pragma unroll
    for(int i=0;i<4;i++) As[ac4+i][arow]=aR[i];
    #pragma unroll
    for(int i=0;i<4;i++) Bs[brow][bcol+i]=bR[i];
    __syncthreads();
    if(kb+8<K){ loadA(kb+8); loadB(kb+8); }
    #pragma unroll
    for(int k=0;k<8;k++){
      float a[8], b[8];
      *(float4*)&a[0]=*(const float4*)&As[k][ty*8];
      *(float4*)&a[4]=*(const float4*)&As[k][ty*8+4];
      *(float4*)&b[0]=*(const float4*)&Bs[k][tx*8];
      *(float4*)&b[4]=*(const float4*)&Bs[k][tx*8+4];
      #pragma unroll
      for(int i=0;i<8;i++)
        #pragma unroll
        for(int j=0;j<8;j++) acc[i][j]+=a[i]*b[j];
    }
    __syncthreads();
  }
  #pragma unroll
  for(int i=0;i<8;i++){
    int r=row0+ty*8+i;
    #pragma unroll
    for(int j=0;j<8;j++){
      int c=col0+tx*8+j;
      if(c<N){
        size_t idx=(size_t)r*N+c; float v=acc[i][j];
        if(EPI==0){ if(bias) v+=bias[c]; P[idx]=v; }
        else if(EPI==3){ P[idx]=v; R[idx]=Q[idx]+siluf(v); }
        else if(EPI==7){ P[idx]=v+bias[c]+siluf(Q[idx]); }
      }
    }
  }
}

__global__ void wvr_k(const float* __restrict__ Wv, float* __restrict__ WvR){
  int i=blockIdx.x*blockDim.x+threadIdx.x;
  if(i>=1024) return;
  int c=i>>7, h=i&127; double s=0.0;
  if(c<3){ for(int r=0;r<64;r++) s+=(double)Wv[(size_t)(3*r+c)*128+h]; }
  else { int cc=c-3; for(int r=0;r<32;r++) s+=(double)Wv[(size_t)(192+5*r+cc)*128+h]; }
  WvR[i]=(float)s;
}
__global__ void transpose_k(const float* __restrict__ in, float* __restrict__ out,int Rr,int Cc){
  int i=blockIdx.x*blockDim.x+threadIdx.x;
  if(i>=Rr*Cc) return;
  out[(size_t)(i%Cc)*Rr+(i/Cc)]=in[i];
}

__global__ void geom_fwd_k(const float* __restrict__ pos, const int* __restrict__ src,
                           const int* __restrict__ dst, float* __restrict__ dbuf,
                           float* __restrict__ envb, float* __restrict__ rbf,
                           float* __restrict__ l1l2)
{
  int e=blockIdx.x*blockDim.x+threadIdx.x;
  if(e>=E_EDGES) return;
  int s=src[e], t=dst[e];
  float bx=pos[3*s]-pos[3*t], by=pos[3*s+1]-pos[3*t+1], bz=pos[3*s+2]-pos[3*t+2];
  float df=sqrtf(bx*bx+by*by+bz*bz+1e-12f);
  dbuf[e]=df;
  double d=(double)df, xx=d*0.2, env=0.0;
  if(df<5.f){ double x5=xx*xx*xx*xx*xx; env=1.0-21.0*x5+35.0*x5*xx-15.0*x5*xx*xx; }
  envb[e]=(float)env;
  double a=sqrt(0.4), invd=1.0/d;
  #pragma unroll
  for(int k=1;k<=20;k++)
    rbf[(size_t)e*20+k-1]=(float)(a*sin((double)k*(PI_D/5.0)*d)*invd);
  double ux=(double)bx*invd, uy=(double)by*invd, uz=(double)bz*invd;
  const double s3=1.7320508075688772935;
  float* L=l1l2+(size_t)e*8;
  L[0]=(float)uy; L[1]=(float)uz; L[2]=(float)ux;
  L[3]=(float)(s3*ux*uy); L[4]=(float)(s3*uy*uz); L[5]=(float)(0.5*(3.0*uz*uz-1.0));
  L[6]=(float)(s3*ux*uz); L[7]=(float)(0.5*s3*(ux*ux-uy*uy));
}

__global__ void hist_k(const int* __restrict__ neo,int* __restrict__ ds_,int* __restrict__ dd_){
  int i=blockIdx.x*blockDim.x+threadIdx.x;
  if(i>=LE_EDGES) return;
  atomicAdd(&ds_[neo[i]],1); atomicAdd(&dd_[neo[LE_EDGES+i]],1);
}
__global__ void hist_atom_k(const int* __restrict__ src,const int* __restrict__ dst,
                            int* __restrict__ hs,int* __restrict__ hd){
  int i=blockIdx.x*blockDim.x+threadIdx.x;
  if(i>=E_EDGES) return;
  atomicAdd(&hs[src[i]],1); atomicAdd(&hd[dst[i]],1);
}
__global__ void scan_k(const int* __restrict__ in,int* __restrict__ out,int n){
  __shared__ int wsum[32]; __shared__ int carry;
  int tid=threadIdx.x, lane=tid&31, wid=tid>>5;
  if(tid==0) carry=0;
  __syncthreads();
  for(int base=0;base<n;base+=1024){
    int i=base+tid, v=(i<n)?in[i]:0, x=v;
    #pragma unroll
    for(int o=1;o<32;o<<=1){ int y=__shfl_up_sync(~0u,x,o); if(lane>=o) x+=y; }
    if(lane==31) wsum[wid]=x;
    __syncthreads();
    if(wid==0){
      int s=wsum[lane];
      #pragma unroll
      for(int o=1;o<32;o<<=1){ int y=__shfl_up_sync(~0u,s,o); if(lane>=o) s+=y; }
      wsum[lane]=s;
    }
    __syncthreads();
    int wo=(wid>0)?wsum[wid-1]:0;
    if(i<n) out[i]=carry+wo+x-v;
    __syncthreads();
    if(tid==0) carry+=wsum[31];
    __syncthreads();
  }
  if(tid==0) out[n]=carry;
}
__global__ void fill_k(const int* __restrict__ neo,int* __restrict__ cs,int* __restrict__ cd,
                       int* __restrict__ csr_s,int* __restrict__ csr_d){
  int i=blockIdx.x*blockDim.x+threadIdx.x;
  if(i>=LE_EDGES) return;
  int s=neo[i], t=neo[LE_EDGES+i];
  csr_d[atomicAdd(&cd[t],1)]=s;
  csr_s[atomicAdd(&cs[s],1)]=t;
}
__global__ void fill_atom_k(const int* __restrict__ src,const int* __restrict__ dst,
                            int* __restrict__ cs,int* __restrict__ cd,
                            int* __restrict__ ls,int* __restrict__ ld){
  int e=blockIdx.x*blockDim.x+threadIdx.x;
  if(e>=E_EDGES) return;
  ls[atomicAdd(&cs[src[e]],1)]=e;
  ld[atomicAdd(&cd[dst[e]],1)]=e;
}
__global__ void sort_atom_k(const int* __restrict__ rp,int* __restrict__ lst){
  int a=blockIdx.x*blockDim.x+threadIdx.x;
  if(a>=N_ATOMS) return;
  int b=rp[a], en=rp[a+1];
  for(int i=b+1;i<en;i++){
    int v=lst[i], j=i-1;
    while(j>=b && lst[j]>v){ lst[j+1]=lst[j]; j--; }
    lst[j+1]=v;
  }
}
__global__ void csr_gather_k(const int* __restrict__ rp,const int* __restrict__ cols,
                             const float* __restrict__ sm,float* __restrict__ dm){
  int w=(blockIdx.x*blockDim.x+threadIdx.x)>>5, lane=threadIdx.x&31;
  if(w>=E_EDGES) return;
  int beg=rp[w], end=rp[w+1];
  double a0=0,a1=0,a2=0,a3=0;
  for(int j=beg;j<end;j++){
    float4 v=*(const float4*)(sm+(size_t)cols[j]*128+lane*4);
    a0+=v.x;a1+=v.y;a2+=v.z;a3+=v.w;
  }
  *(float4*)(dm+(size_t)w*128+lane*4)=make_float4((float)a0,(float)a1,(float)a2,(float)a3);
}
__global__ void fwd_xg_k(const float4* __restrict__ x,const float4* __restrict__ g,float4* __restrict__ xg){
  int i=blockIdx.x*blockDim.x+threadIdx.x;
  if(i>=EH/4) return;
  float4 xv=x[i],gv=g[i],r;
  r.x=xv.x*siluf(gv.x); r.y=xv.y*siluf(gv.y); r.z=xv.z*siluf(gv.z); r.w=xv.w*siluf(gv.w);
  xg[i]=r;
}
__global__ void energy_k(const float* __restrict__ x3,const float* __restrict__ envb,
                         const float* __restrict__ w_out,const int* __restrict__ src,
                         const int* __restrict__ batch,double* __restrict__ denvD,
                         float* __restrict__ results){
  __shared__ float gsum[NGRAPH];
  int tid=threadIdx.x;
  if(tid<NGRAPH) gsum[tid]=0.f;
  __syncthreads();
  int w=(blockIdx.x*256+tid)>>5, lane=tid&31;
  if(w<E_EDGES){
    float4 xv=*(const float4*)(x3+(size_t)w*128+lane*4);
    float4 wv=((const float4*)w_out)[lane];
    double v=(double)xv.x*wv.x+(double)xv.y*wv.y+(double)xv.z*wv.z+(double)xv.w*wv.w;
    #pragma unroll
    for(int o=16;o>0;o>>=1) v+=__shfl_down_sync(~0u,v,o);
    if(lane==0){ denvD[w]=v; atomicAdd(&gsum[batch[src[w]]],(float)(v*(double)envb[w])); }
  }
  __syncthreads();
  if(tid<NGRAPH && gsum[tid]!=0.f) atomicAdd(&results[tid],gsum[tid]);
}
__global__ void b1b_k(const float* __restrict__ envb,const float* __restrict__ w_out,float* __restrict__ dx){
  int i=blockIdx.x*blockDim.x+threadIdx.x;
  if(i>=EH/4) return;
  int e=i>>5, h4=i&31;
  float4 wv=((const float4*)w_out)[h4]; float ev=envb[e];
  ((float4*)dx)[i]=make_float4(ev*wv.x,ev*wv.y,ev*wv.z,ev*wv.w);
}
__global__ void b5_k(const float4* __restrict__ A,const float4* __restrict__ x,
                     const float4* __restrict__ g,float4* __restrict__ dx,float4* __restrict__ dgp){
  int i=blockIdx.x*blockDim.x+threadIdx.x;
  if(i>=EH/4) return;
  float4 a=A[i],xv=x[i],gv=g[i],d=dx[i],nd,ng;
  nd.x=d.x+a.x*siluf(gv.x); ng.x=a.x*xv.x*silupf(gv.x);
  nd.y=d.y+a.y*siluf(gv.y); ng.y=a.y*xv.y*silupf(gv.y);
  nd.z=d.z+a.z*siluf(gv.z); ng.z=a.z*xv.z*silupf(gv.z);
  nd.w=d.w+a.w*siluf(gv.w); ng.w=a.w*xv.w*silupf(gv.w);
  dx[i]=nd; dgp[i]=ng;
}
__global__ void b7b_k(const float* __restrict__ de,const float* __restrict__ ea,
                      const float* __restrict__ gr_,const float* __restrict__ envb,
                      double* __restrict__ denvD,float* __restrict__ eg32){
  int w=(blockIdx.x*256+threadIdx.x)>>5, lane=threadIdx.x&31;
  if(w>=E_EDGES) return;
  const float* dr=de+(size_t)w*169;
  const float* er=ea+(size_t)w*169;
  const float* gr=gr_+(size_t)w*507;
  double env=(double)envb[w], ae=0,a0=0,a1=0,a2=0;
  for(int f=lane;f<169;f+=32){
    double dv=(double)dr[f];
    ae+=dv*(double)er[f];
    double ev=dv*env;
    a0+=ev*(double)gr[f]; a1+=ev*(double)gr[169+f]; a2+=ev*(double)gr[338+f];
  }
  #pragma unroll
  for(int o=16;o>0;o>>=1){
    ae+=__shfl_down_sync(~0u,ae,o); a0+=__shfl_down_sync(~0u,a0,o);
    a1+=__shfl_down_sync(~0u,a1,o); a2+=__shfl_down_sync(~0u,a2,o);
  }
  if(lane==0){
    denvD[w]+=ae;
    eg32[(size_t)w*3]=(float)a0; eg32[(size_t)w*3+1]=(float)a1; eg32[(size_t)w*3+2]=(float)a2;
  }
}
__global__ void b8_k(const float* __restrict__ dx0,const float* __restrict__ spre,
                     const float* __restrict__ WvR,double* __restrict__ dlD){
  __shared__ float wv[1024];
  int tid=threadIdx.x;
  for(int i=tid;i<1024;i+=256) wv[i]=WvR[i];
  __syncthreads();
  int w=(blockIdx.x*256+tid)>>5, lane=tid&31;
  if(w>=E_EDGES) return;
  double acc[8]={0,0,0,0,0,0,0,0};
  float4 dv=*(const float4*)(dx0+(size_t)w*128+lane*4);
  float4 sp=*(const float4*)(spre+(size_t)w*128+lane*4);
  float dvv[4]={dv.x*silupf(sp.x),dv.y*silupf(sp.y),dv.z*silupf(sp.z),dv.w*silupf(sp.w)};
  #pragma unroll
  for(int j=0;j<4;j++){
    int h=lane*4+j; double tt=(double)dvv[j];
    #pragma unroll
    for(int k=0;k<8;k++) acc[k]+=tt*(double)wv[k*128+h];
  }
  #pragma unroll
  for(int k=0;k<8;k++){
    double v=acc[k];
    #pragma unroll
    for(int o=16;o>0;o>>=1) v+=__shfl_down_sync(~0u,v,o);
    if(lane==0) dlD[(size_t)w*8+k]=v;
  }
}

__global__ void edge_grad_k(const float* __restrict__ dbuf,const double* __restrict__ denvD,
                            const float* __restrict__ r0,const float* __restrict__ r1,
                            const float* __restrict__ r2,const double* __restrict__ dlD,
                            const float* __restrict__ l1l2,float* __restrict__ g32){
  int e=blockIdx.x*blockDim.x+threadIdx.x;
  if(e>=E_EDGES) return;
  double d=(double)dbuf[e];
  double dd=0.0, xx=d*0.2;
  if(d<5.0){
    double x4=xx*xx; x4*=x4;
    dd=denvD[e]*x4*(-105.0+xx*(210.0-105.0*xx))*0.2;
  }
  double a=sqrt(0.4), invd=1.0/d, invd2=invd*invd;
  #pragma unroll
  for(int k=1;k<=20;k++){
    double b=(double)k*(PI_D/5.0);
    double sn,cs; sincos(b*d,&sn,&cs);
    double dr=(double)r0[(size_t)e*20+k-1]+(double)r1[(size_t)e*20+k-1]+(double)r2[(size_t)e*20+k-1];
    dd+=dr*a*(b*cs*d-sn)*invd2;
  }
  const float* L=l1l2+(size_t)e*8;
  double uy=L[0], uz=L[1], ux=L[2];
  const double* DL=dlD+(size_t)e*8;
  const double s3=1.7320508075688772935;
  double dux=DL[2]+s3*uy*DL[3]+s3*uz*DL[6]+s3*ux*DL[7];
  double duy=DL[0]+s3*ux*DL[3]+s3*uz*DL[4]-s3*uy*DL[7];
  double duz=DL[1]+s3*uy*DL[4]+3.0*uz*DL[5]+s3*ux*DL[6];
  double ud=ux*dux+uy*duy+uz*duz;
  g32[(size_t)e*3  ]=(float)((dux-ux*ud)*invd+dd*ux);
  g32[(size_t)e*3+1]=(float)((duy-uy*ud)*invd+dd*uy);
  g32[(size_t)e*3+2]=(float)((duz-uz*ud)*invd+dd*uz);
}

// Reference-emulating fp32 per-atom ordered accumulation (self-loops included)
__global__ void force_k(const int* __restrict__ rpS,const int* __restrict__ lsS,
                        const int* __restrict__ rpD,const int* __restrict__ lsD,
                        const float* __restrict__ g32,const float* __restrict__ eg32,
                        float* __restrict__ outF){
  int a=blockIdx.x*blockDim.x+threadIdx.x;
  if(a>=N_ATOMS) return;
  int sb=rpS[a], se=rpS[a+1], db=rpD[a], de_=rpD[a+1];
  float s1x=0.f,s1y=0.f,s1z=0.f;
  for(int j=sb;j<se;j++){ int e=lsS[j]; s1x+=g32[(size_t)e*3]; s1y+=g32[(size_t)e*3+1]; s1z+=g32[(size_t)e*3+2]; }
  float s2x=0.f,s2y=0.f,s2z=0.f;
  for(int j=db;j<de_;j++){ int e=lsD[j]; s2x-=g32[(size_t)e*3]; s2y-=g32[(size_t)e*3+1]; s2z-=g32[(size_t)e*3+2]; }
  float apx=s1x+s2x, apy=s1y+s2y, apz=s1z+s2z;
  float Sx=0.f,Sy=0.f,Sz=0.f;
  for(int j=sb;j<se;j++){ int e=lsS[j]; Sx+=eg32[(size_t)e*3]; Sy+=eg32[(size_t)e*3+1]; Sz+=eg32[(size_t)e*3+2]; }
  for(int j=db;j<de_;j++){ int e=lsD[j]; Sx-=eg32[(size_t)e*3]; Sy-=eg32[(size_t)e*3+1]; Sz-=eg32[(size_t)e*3+2]; }
  outF[3*a  ]=-(apx+Sx);
  outF[3*a+1]=-(apy+Sy);
  outF[3*a+2]=-(apz+Sz);
}

extern "C" void kernel_launch(void* const* d_in, const int* in_sizes, int n_in,
                              void* d_out, int out_size)
{
  const float* atom_pos=(const float*)d_in[0];
  const float* edge_attr=(const float*)d_in[1];
  const float* eagrad=(const float*)d_in[2];
  const float* W_mat=(const float*)d_in[3];
  const float* b_mat=(const float*)d_in[4];
  const float* W_emb=(const float*)d_in[5];
  const float* b_emb=(const float*)d_in[6];
  const float* Wv=(const float*)d_in[7];
  const float* Wr=(const float*)d_in[8];
  const float* Wx=(const float*)d_in[9];
  const float* w_out=(const float*)d_in[10];
  const int* edge_index=(const int*)d_in[11];
  const int* neo=(const int*)d_in[12];
  const int* batch=(const int*)d_in[13];
  float* out=(float*)d_out;
  const int* src=edge_index;
  const int* dst=edge_index+E_EDGES;
  const int E=E_EDGES;

  void* basev=nullptr;
  cudaGetSymbolAddress(&basev, g_scratch);
  float* bf=(float*)basev;
  size_t o=0;
  auto F=[&](size_t n){ float* p=bf+o; o+=n; return p; };
  float* pre1=F(EH); float* spre=F(EH);
  float* x0=F(EH); float* x1=F(EH); float* x2=F(EH); float* x3=F(EH);
  float* gpre0=F(EH); float* gpre1=F(EH); float* gpre2=F(EH);
  float* z0=F(EH); float* z1=F(EH); float* z2=F(EH);
  float* t1=F(EH); float* t2=F(EH); float* t3=F(EH);
  float* de=F((size_t)E*169);
  float* rbf=F((size_t)E*20);
  float* drbf0=F((size_t)E*20); float* drbf1=F((size_t)E*20); float* drbf2=F((size_t)E*20);
  float* l1l2=F((size_t)E*8);
  float* dbuf=F(E); float* envb=F(E);
  float* g32=F((size_t)E*3); float* eg32=F((size_t)E*3);
  float* WvR=F(1024); float* WembT=F(16384); float* WmatT=F(21632);
  float* WxT=F(3*16384); float* WrT=F(3*2560);
  o=(o+1)&~(size_t)1;
  double* denvD=(double*)(bf+o); o+=2*(size_t)E;
  double* dlD=(double*)(bf+o); o+=2*(size_t)E*8;
  int* bi=(int*)(bf+o);
  size_t oi=0;
  auto I=[&](size_t n){ int* p=bi+oi; oi+=n; return p; };
  int* rp_dst=I(E+1); int* rp_src=I(E+1);
  int* cur_dst=I(E); int* cur_src=I(E);
  int* csr_dst=I(LE_EDGES); int* csr_src=I(LE_EDGES);
  int* rpAS=I(N_ATOMS+1); int* rpAD=I(N_ATOMS+1);
  int* curAS=I(N_ATOMS); int* curAD=I(N_ATOMS);
  int* lsAS=I(E); int* lsAD=I(E);

  float* dx=x3;
  float* xs[4]={x0,x1,x2,x3};
  float* gpres[3]={gpre0,gpre1,gpre2};
  float* zs[3]={z0,z1,z2};
  float* drbfs[3]={drbf0,drbf1,drbf2};

  cudaMemsetAsync(out,0,(size_t)out_size*sizeof(float));
  cudaMemsetAsync(cur_dst,0,(size_t)E*sizeof(int));
  cudaMemsetAsync(cur_src,0,(size_t)E*sizeof(int));
  cudaMemsetAsync(curAS,0,(size_t)N_ATOMS*sizeof(int));
  cudaMemsetAsync(curAD,0,(size_t)N_ATOMS*sizeof(int));

  wvr_k<<<4,256>>>(Wv,WvR);
  transpose_k<<<64,256>>>(W_emb,WembT,128,128);
  transpose_k<<<(169*128+255)/256,256>>>(W_mat,WmatT,169,128);
  for(int l=0;l<3;l++){
    transpose_k<<<64,256>>>(Wx+(size_t)l*16384,WxT+(size_t)l*16384,128,128);
    transpose_k<<<10,256>>>(Wr+(size_t)l*2560,WrT+(size_t)l*2560,20,128);
  }
  geom_fwd_k<<<E/256,256>>>(atom_pos,src,dst,dbuf,envb,rbf,l1l2);

  hist_k<<<LE_EDGES/256,256>>>(neo,cur_src,cur_dst);
  scan_k<<<1,1024>>>(cur_dst,rp_dst,E);
  scan_k<<<1,1024>>>(cur_src,rp_src,E);
  cudaMemcpyAsync(cur_dst,rp_dst,(size_t)E*sizeof(int),cudaMemcpyDeviceToDevice);
  cudaMemcpyAsync(cur_src,rp_src,(size_t)E*sizeof(int),cudaMemcpyDeviceToDevice);
  fill_k<<<LE_EDGES/256,256>>>(neo,cur_src,cur_dst,csr_src,csr_dst);

  hist_atom_k<<<E/256,256>>>(src,dst,curAS,curAD);
  scan_k<<<1,1024>>>(curAS,rpAS,N_ATOMS);
  scan_k<<<1,1024>>>(curAD,rpAD,N_ATOMS);
  cudaMemcpyAsync(curAS,rpAS,(size_t)N_ATOMS*sizeof(int),cudaMemcpyDeviceToDevice);
  cudaMemcpyAsync(curAD,rpAD,(size_t)N_ATOMS*sizeof(int),cudaMemcpyDeviceToDevice);
  fill_atom_k<<<E/256,256>>>(src,dst,curAS,curAD,lsAS,lsAD);
  sort_atom_k<<<(N_ATOMS+255)/256,256>>>(rpAS,lsAS);
  sort_atom_k<<<(N_ATOMS+255)/256,256>>>(rpAD,lsAD);

  dim3 gN1(E/128,1), gN2(E/128,2);
  gemm_k<2,0><<<gN1,256>>>(edge_attr,nullptr,envb,W_mat,b_mat,nullptr,pre1,nullptr,E,128,169);
  gemm_k<0,0><<<gN1,256>>>(l1l2,nullptr,nullptr,WvR,nullptr,nullptr,spre,nullptr,E,128,8);
  gemm_k<1,7><<<gN1,256>>>(pre1,nullptr,nullptr,W_emb,b_emb,spre,x0,nullptr,E,128,128);
  for(int l=0;l<3;l++){
    gemm_k<0,0><<<gN1,256>>>(rbf,nullptr,nullptr,Wr+(size_t)l*2560,nullptr,nullptr,gpres[l],nullptr,E,128,20);
    fwd_xg_k<<<EH/1024,256>>>((const float4*)xs[l],(const float4*)gpres[l],(float4*)t1);
    csr_gather_k<<<E*32/256,256>>>(rp_dst,csr_dst,t1,t2);
    gemm_k<0,3><<<gN1,256>>>(t2,nullptr,nullptr,Wx+(size_t)l*16384,nullptr,xs[l],zs[l],xs[l+1],E,128,128);
  }
  energy_k<<<E*32/256,256>>>(x3,envb,w_out,src,batch,denvD,out);

  b1b_k<<<EH/1024,256>>>(envb,w_out,dx);
  for(int l=2;l>=0;l--){
    gemm_k<3,0><<<gN1,256>>>(dx,zs[l],nullptr,WxT+(size_t)l*16384,nullptr,nullptr,t1,nullptr,E,128,128);
    csr_gather_k<<<E*32/256,256>>>(rp_src,csr_src,t1,t2);
    b5_k<<<EH/1024,256>>>((const float4*)t2,(const float4*)xs[l],(const float4*)gpres[l],(float4*)dx,(float4*)t3);
    gemm_k<0,0><<<gN1,256>>>(t3,nullptr,nullptr,WrT+(size_t)l*2560,nullptr,nullptr,drbfs[l],nullptr,E,20,128);
  }
  b8_k<<<E*32/256,256>>>(dx,spre,WvR,dlD);
  gemm_k<0,0><<<gN1,256>>>(dx,nullptr,nullptr,WembT,nullptr,nullptr,t1,nullptr,E,128,128);
  gemm_k<3,0><<<gN2,256>>>(t1,pre1,nullptr,WmatT,nullptr,nullptr,de,nullptr,E,169,128);
  b7b_k<<<E*32/256,256>>>(de,edge_attr,eagrad,envb,denvD,eg32);
  edge_grad_k<<<E/256,256>>>(dbuf,denvD,drbf0,drbf1,drbf2,dlD,l1l2,g32);
  force_k<<<(N_ATOMS+255)/256,256>>>(rpAS,lsAS,rpAD,lsAD,g32,eg32,out+NGRAPH);
}

// round 17
// speedup vs baseline: 1.4111x; 1.4111x over previous
#include <cuda_runtime.h>
#include <math.h>
#include <stdint.h>

#define E_EDGES 128000
#define N_ATOMS 8000
#define LE_EDGES 512000
#define EH 16384000
#define NGRAPH 64
#define PI_D 3.14159265358979323846

static __device__ __align__(256) unsigned char g_scratch[1245000000];

__device__ __forceinline__ float sigf(float x){ return 1.f/(1.f+expf(-x)); }
__device__ __forceinline__ float siluf(float x){ return x*sigf(x); }
__device__ __forceinline__ float silupf(float x){ float s=sigf(x); return s*(1.f+x*(1.f-s)); }

// SGEMM (R14-proven): C=op(A)@B, BM64 BN128 BK16, 256 thr, 8x4/thread.
// AMODE:0 plain,1 silu,2 rowscale,3 silu'(A2)
// EPI: 0 P=acc(+bias)  3 P=acc,R=Q+silu(acc)  7 P=acc+bias+silu(Q)
template<int AMODE,int EPI>
__global__ __launch_bounds__(256)
void gemm_k(const float* __restrict__ A, const float* __restrict__ A2,
            const float* __restrict__ rs, const float* __restrict__ B,
            const float* __restrict__ bias, const float* __restrict__ Q,
            float* __restrict__ P, float* __restrict__ R, int M,int N,int K)
{
  __shared__ float As[16][64];
  __shared__ float4 Bs[16][32];
  int tid=threadIdx.x, tx=tid&31, ty=tid>>5;
  int row0=blockIdx.x*64, col0=blockIdx.y*128;
  float acc[8][4];
  #pragma unroll
  for(int i=0;i<8;i++){ acc[i][0]=0;acc[i][1]=0;acc[i][2]=0;acc[i][3]=0; }
  int arow=tid>>2, acol4=(tid&3)*4, brow=tid>>4, bcol=(tid&15)*8;
  float rsv=(AMODE==2)?rs[row0+arow]:0.f;
  for(int kb=0;kb<K;kb+=16){
    #pragma unroll
    for(int i=0;i<4;i++){
      int k=kb+acol4+i; float v=0.f;
      if(k<K){
        size_t ai=(size_t)(row0+arow)*K+k; v=A[ai];
        if(AMODE==1) v=siluf(v); else if(AMODE==2) v*=rsv;
        else if(AMODE==3) v*=silupf(A2[ai]);
      }
      As[acol4+i][arow]=v;
    }
    #pragma unroll
    for(int i=0;i<8;i++){
      int k=kb+brow, c=col0+bcol+i;
      ((float*)&Bs[brow][0])[bcol+i]=(k<K&&c<N)?B[(size_t)k*N+c]:0.f;
    }
    __syncthreads();
    #pragma unroll
    for(int k=0;k<16;k++){
      float a[8];
      *(float4*)&a[0]=*(const float4*)&As[k][ty*8];
      *(float4*)&a[4]=*(const float4*)&As[k][ty*8+4];
      float4 b=Bs[k][tx];
      #pragma unroll
      for(int i=0;i<8;i++){
        acc[i][0]+=a[i]*b.x; acc[i][1]+=a[i]*b.y;
        acc[i][2]+=a[i]*b.z; acc[i][3]+=a[i]*b.w;
      }
    }
    __syncthreads();
  }
  #pragma unroll
  for(int i=0;i<8;i++){
    int r=row0+ty*8+i;
    #pragma unroll
    for(int j=0;j<4;j++){
      int c=col0+tx*4+j;
      if(c<N){
        size_t idx=(size_t)r*N+c; float v=acc[i][j];
        if(EPI==0){ if(bias) v+=bias[c]; P[idx]=v; }
        else if(EPI==3){ P[idx]=v; R[idx]=Q[idx]+siluf(v); }
        else if(EPI==7){ P[idx]=v+bias[c]+siluf(Q[idx]); }
      }
    }
  }
}

// fused weight prep: WvR + all transposes, one launch
__global__ void prep_all_k(const float* __restrict__ Wv,float* __restrict__ WvR,
                           const float* __restrict__ W_emb,float* __restrict__ WembT,
                           const float* __restrict__ W_mat,float* __restrict__ WmatT,
                           const float* __restrict__ Wx,float* __restrict__ WxT,
                           const float* __restrict__ Wr,float* __restrict__ WrT){
  int i=blockIdx.x*blockDim.x+threadIdx.x;
  if(i<1024){
    int c=i>>7, h=i&127; double s=0.0;
    if(c<3){ for(int r=0;r<64;r++) s+=(double)Wv[(size_t)(3*r+c)*128+h]; }
    else { int cc=c-3; for(int r=0;r<32;r++) s+=(double)Wv[(size_t)(192+5*r+cc)*128+h]; }
    WvR[i]=(float)s; return;
  }
  i-=1024;
  if(i<16384){ int r=i>>7, c=i&127; WembT[c*128+r]=W_emb[i]; return; }
  i-=16384;
  if(i<21632){ int r=i/128, c=i%128; WmatT[(size_t)c*169+r]=W_mat[i]; return; }
  i-=21632;
  if(i<49152){
    int l=i>>14, j=i&16383, r=j>>7, c=j&127;
    WxT[(size_t)l*16384+c*128+r]=Wx[(size_t)l*16384+j]; return;
  }
  i-=49152;
  if(i<7680){
    int l=i/2560, j=i%2560, r=j/128, c=j%128;
    WrT[(size_t)l*2560+c*20+r]=Wr[(size_t)l*2560+j];
  }
}

// geometry forward: 1 fp64 sincos + Chebyshev recurrence for the 20 bessel sins
__global__ void geom_fwd_k(const float* __restrict__ pos, const int* __restrict__ src,
                           const int* __restrict__ dst, float* __restrict__ dbuf,
                           float* __restrict__ envb, float* __restrict__ rbf,
                           float* __restrict__ l1l2)
{
  int e=blockIdx.x*blockDim.x+threadIdx.x;
  if(e>=E_EDGES) return;
  int s=src[e], t=dst[e];
  float bx=pos[3*s]-pos[3*t], by=pos[3*s+1]-pos[3*t+1], bz=pos[3*s+2]-pos[3*t+2];
  float df=sqrtf(bx*bx+by*by+bz*bz+1e-12f);
  dbuf[e]=df;
  double d=(double)df, xx=d*0.2, env=0.0;
  if(df<5.f){ double x5=xx*xx*xx*xx*xx; env=1.0-21.0*x5+35.0*x5*xx-15.0*x5*xx*xx; }
  envb[e]=(float)env;
  double a=sqrt(0.4), invd=1.0/d;
  double th=(PI_D/5.0)*d, s1,c1;
  sincos(th,&s1,&c1);
  double twoc=2.0*c1, skm1=s1, skm2=0.0;
  rbf[(size_t)e*20]=(float)(a*s1*invd);
  #pragma unroll
  for(int k=2;k<=20;k++){
    double sk=twoc*skm1-skm2;
    rbf[(size_t)e*20+k-1]=(float)(a*sk*invd);
    skm2=skm1; skm1=sk;
  }
  double ux=(double)bx*invd, uy=(double)by*invd, uz=(double)bz*invd;
  const double s3=1.7320508075688772935;
  float* L=l1l2+(size_t)e*8;
  L[0]=(float)uy; L[1]=(float)uz; L[2]=(float)ux;
  L[3]=(float)(s3*ux*uy); L[4]=(float)(s3*uy*uz); L[5]=(float)(0.5*(3.0*uz*uz-1.0));
  L[6]=(float)(s3*ux*uz); L[7]=(float)(0.5*s3*(ux*ux-uy*uy));
}

__global__ void hist_k(const int* __restrict__ neo,int* __restrict__ ds_,int* __restrict__ dd_){
  int i=blockIdx.x*blockDim.x+threadIdx.x;
  if(i>=LE_EDGES) return;
  atomicAdd(&ds_[neo[i]],1); atomicAdd(&dd_[neo[LE_EDGES+i]],1);
}
__global__ void hist_atom_k(const int* __restrict__ src,const int* __restrict__ dst,
                            int* __restrict__ hs,int* __restrict__ hd){
  int i=blockIdx.x*blockDim.x+threadIdx.x;
  if(i>=E_EDGES) return;
  atomicAdd(&hs[src[i]],1); atomicAdd(&hd[dst[i]],1);
}
__global__ void scan_k(const int* __restrict__ in,int* __restrict__ out,int n){
  __shared__ int wsum[32]; __shared__ int carry;
  int tid=threadIdx.x, lane=tid&31, wid=tid>>5;
  if(tid==0) carry=0;
  __syncthreads();
  for(int base=0;base<n;base+=1024){
    int i=base+tid, v=(i<n)?in[i]:0, x=v;
    #pragma unroll
    for(int o=1;o<32;o<<=1){ int y=__shfl_up_sync(~0u,x,o); if(lane>=o) x+=y; }
    if(lane==31) wsum[wid]=x;
    __syncthreads();
    if(wid==0){
      int s=wsum[lane];
      #pragma unroll
      for(int o=1;o<32;o<<=1){ int y=__shfl_up_sync(~0u,s,o); if(lane>=o) s+=y; }
      wsum[lane]=s;
    }
    __syncthreads();
    int wo=(wid>0)?wsum[wid-1]:0;
    if(i<n) out[i]=carry+wo+x-v;
    __syncthreads();
    if(tid==0) carry+=wsum[31];
    __syncthreads();
  }
  if(tid==0) out[n]=carry;
}
__global__ void fill_k(const int* __restrict__ neo,int* __restrict__ cs,int* __restrict__ cd,
                       int* __restrict__ csr_s,int* __restrict__ csr_d){
  int i=blockIdx.x*blockDim.x+threadIdx.x;
  if(i>=LE_EDGES) return;
  int s=neo[i], t=neo[LE_EDGES+i];
  csr_d[atomicAdd(&cd[t],1)]=s;
  csr_s[atomicAdd(&cs[s],1)]=t;
}
__global__ void fill_atom_k(const int* __restrict__ src,const int* __restrict__ dst,
                            int* __restrict__ cs,int* __restrict__ cd,
                            int* __restrict__ ls,int* __restrict__ ld){
  int e=blockIdx.x*blockDim.x+threadIdx.x;
  if(e>=E_EDGES) return;
  ls[atomicAdd(&cs[src[e]],1)]=e;
  ld[atomicAdd(&cd[dst[e]],1)]=e;
}
__global__ void sort_atom_k(const int* __restrict__ rp,int* __restrict__ lst){
  int a=blockIdx.x*blockDim.x+threadIdx.x;
  if(a>=N_ATOMS) return;
  int b=rp[a], en=rp[a+1];
  for(int i=b+1;i<en;i++){
    int v=lst[i], j=i-1;
    while(j>=b && lst[j]>v){ lst[j+1]=lst[j]; j--; }
    lst[j+1]=v;
  }
}
// fp32 accumulation (ref is fp32 segment-sum; fp64 here costs DADD throughput)
__global__ void csr_gather_k(const int* __restrict__ rp,const int* __restrict__ cols,
                             const float* __restrict__ sm,float* __restrict__ dm){
  int w=(blockIdx.x*blockDim.x+threadIdx.x)>>5, lane=threadIdx.x&31;
  if(w>=E_EDGES) return;
  int beg=rp[w], end=rp[w+1];
  float a0=0.f,a1=0.f,a2=0.f,a3=0.f;
  for(int j=beg;j<end;j++){
    float4 v=*(const float4*)(sm+(size_t)cols[j]*128+lane*4);
    a0+=v.x;a1+=v.y;a2+=v.z;a3+=v.w;
  }
  *(float4*)(dm+(size_t)w*128+lane*4)=make_float4(a0,a1,a2,a3);
}
__global__ void fwd_xg_k(const float4* __restrict__ x,const float4* __restrict__ g,float4* __restrict__ xg){
  int i=blockIdx.x*blockDim.x+threadIdx.x;
  if(i>=EH/4) return;
  float4 xv=x[i],gv=g[i],r;
  r.x=xv.x*siluf(gv.x); r.y=xv.y*siluf(gv.y); r.z=xv.z*siluf(gv.z); r.w=xv.w*siluf(gv.w);
  xg[i]=r;
}
__global__ void energy_k(const float* __restrict__ x3,const float* __restrict__ envb,
                         const float* __restrict__ w_out,const int* __restrict__ src,
                         const int* __restrict__ batch,double* __restrict__ denvD,
                         float* __restrict__ results){
  __shared__ float gsum[NGRAPH];
  int tid=threadIdx.x;
  if(tid<NGRAPH) gsum[tid]=0.f;
  __syncthreads();
  int w=(blockIdx.x*256+tid)>>5, lane=tid&31;
  if(w<E_EDGES){
    float4 xv=*(const float4*)(x3+(size_t)w*128+lane*4);
    float4 wv=((const float4*)w_out)[lane];
    double v=(double)xv.x*wv.x+(double)xv.y*wv.y+(double)xv.z*wv.z+(double)xv.w*wv.w;
    #pragma unroll
    for(int o=16;o>0;o>>=1) v+=__shfl_down_sync(~0u,v,o);
    if(lane==0){ denvD[w]=v; atomicAdd(&gsum[batch[src[w]]],(float)(v*(double)envb[w])); }
  }
  __syncthreads();
  if(tid<NGRAPH && gsum[tid]!=0.f) atomicAdd(&results[tid],gsum[tid]);
}
__global__ void b1b_k(const float* __restrict__ envb,const float* __restrict__ w_out,float* __restrict__ dx){
  int i=blockIdx.x*blockDim.x+threadIdx.x;
  if(i>=EH/4) return;
  int e=i>>5, h4=i&31;
  float4 wv=((const float4*)w_out)[h4]; float ev=envb[e];
  ((float4*)dx)[i]=make_float4(ev*wv.x,ev*wv.y,ev*wv.z,ev*wv.w);
}
__global__ void b5_k(const float4* __restrict__ A,const float4* __restrict__ x,
                     const float4* __restrict__ g,float4* __restrict__ dx,float4* __restrict__ dgp){
  int i=blockIdx.x*blockDim.x+threadIdx.x;
  if(i>=EH/4) return;
  float4 a=A[i],xv=x[i],gv=g[i],d=dx[i],nd,ng;
  nd.x=d.x+a.x*siluf(gv.x); ng.x=a.x*xv.x*silupf(gv.x);
  nd.y=d.y+a.y*siluf(gv.y); ng.y=a.y*xv.y*silupf(gv.y);
  nd.z=d.z+a.z*siluf(gv.z); ng.z=a.z*xv.z*silupf(gv.z);
  nd.w=d.w+a.w*siluf(gv.w); ng.w=a.w*xv.w*silupf(gv.w);
  dx[i]=nd; dgp[i]=ng;
}
__global__ void b7b_k(const float* __restrict__ de,const float* __restrict__ ea,
                      const float* __restrict__ gr_,const float* __restrict__ envb,
                      double* __restrict__ denvD,float* __restrict__ eg32){
  int w=(blockIdx.x*256+threadIdx.x)>>5, lane=threadIdx.x&31;
  if(w>=E_EDGES) return;
  const float* dr=de+(size_t)w*169;
  const float* er=ea+(size_t)w*169;
  const float* gr=gr_+(size_t)w*507;
  double env=(double)envb[w], ae=0,a0=0,a1=0,a2=0;
  for(int f=lane;f<169;f+=32){
    double dv=(double)dr[f];
    ae+=dv*(double)er[f];
    double ev=dv*env;
    a0+=ev*(double)gr[f]; a1+=ev*(double)gr[169+f]; a2+=ev*(double)gr[338+f];
  }
  #pragma unroll
  for(int o=16;o>0;o>>=1){
    ae+=__shfl_down_sync(~0u,ae,o); a0+=__shfl_down_sync(~0u,a0,o);
    a1+=__shfl_down_sync(~0u,a1,o); a2+=__shfl_down_sync(~0u,a2,o);
  }
  if(lane==0){
    denvD[w]+=ae;
    eg32[(size_t)w*3]=(float)a0; eg32[(size_t)w*3+1]=(float)a1; eg32[(size_t)w*3+2]=(float)a2;
  }
}
__global__ void b8_k(const float* __restrict__ dx0,const float* __restrict__ spre,
                     const float* __restrict__ WvR,double* __restrict__ dlD){
  __shared__ float wv[1024];
  int tid=threadIdx.x;
  for(int i=tid;i<1024;i+=256) wv[i]=WvR[i];
  __syncthreads();
  int w=(blockIdx.x*256+tid)>>5, lane=tid&31;
  if(w>=E_EDGES) return;
  double acc[8]={0,0,0,0,0,0,0,0};
  float4 dv=*(const float4*)(dx0+(size_t)w*128+lane*4);
  float4 sp=*(const float4*)(spre+(size_t)w*128+lane*4);
  float dvv[4]={dv.x*silupf(sp.x),dv.y*silupf(sp.y),dv.z*silupf(sp.z),dv.w*silupf(sp.w)};
  #pragma unroll
  for(int j=0;j<4;j++){
    int h=lane*4+j; double tt=(double)dvv[j];
    #pragma unroll
    for(int k=0;k<8;k++) acc[k]+=tt*(double)wv[k*128+h];
  }
  #pragma unroll
  for(int k=0;k<8;k++){
    double v=acc[k];
    #pragma unroll
    for(int o=16;o>0;o>>=1) v+=__shfl_down_sync(~0u,v,o);
    if(lane==0) dlD[(size_t)w*8+k]=v;
  }
}

// edge bond-gradient: 1 fp64 sincos + recurrence for sin(k t), cos(k t)
__global__ void edge_grad_k(const float* __restrict__ dbuf,const double* __restrict__ denvD,
                            const float* __restrict__ r0,const float* __restrict__ r1,
                            const float* __restrict__ r2,const double* __restrict__ dlD,
                            const float* __restrict__ l1l2,float* __restrict__ g32){
  int e=blockIdx.x*blockDim.x+threadIdx.x;
  if(e>=E_EDGES) return;
  double d=(double)dbuf[e];
  double dd=0.0, xx=d*0.2;
  if(d<5.0){
    double x4=xx*xx; x4*=x4;
    dd=denvD[e]*x4*(-105.0+xx*(210.0-105.0*xx))*0.2;
  }
  double a=sqrt(0.4), invd=1.0/d, invd2=invd*invd;
  double th=(PI_D/5.0)*d, s1,c1;
  sincos(th,&s1,&c1);
  double twoc=2.0*c1;
  double sk=s1, skm=0.0, ck=c1, ckm=1.0;
  #pragma unroll
  for(int k=1;k<=20;k++){
    double b=(double)k*(PI_D/5.0);
    double dr=(double)r0[(size_t)e*20+k-1]+(double)r1[(size_t)e*20+k-1]+(double)r2[(size_t)e*20+k-1];
    dd+=dr*a*(b*ck*d-sk)*invd2;
    double sn=twoc*sk-skm, cn=twoc*ck-ckm;
    skm=sk; sk=sn; ckm=ck; ck=cn;
  }
  const float* L=l1l2+(size_t)e*8;
  double uy=L[0], uz=L[1], ux=L[2];
  const double* DL=dlD+(size_t)e*8;
  const double s3=1.7320508075688772935;
  double dux=DL[2]+s3*uy*DL[3]+s3*uz*DL[6]+s3*ux*DL[7];
  double duy=DL[0]+s3*ux*DL[3]+s3*uz*DL[4]-s3*uy*DL[7];
  double duz=DL[1]+s3*uy*DL[4]+3.0*uz*DL[5]+s3*ux*DL[6];
  double ud=ux*dux+uy*duy+uz*duz;
  g32[(size_t)e*3  ]=(float)((dux-ux*ud)*invd+dd*ux);
  g32[(size_t)e*3+1]=(float)((duy-uy*ud)*invd+dd*uy);
  g32[(size_t)e*3+2]=(float)((duz-uz*ud)*invd+dd*uz);
}

// Reference-emulating fp32 per-atom ordered accumulation (self-loops included)
__global__ void force_k(const int* __restrict__ rpS,const int* __restrict__ lsS,
                        const int* __restrict__ rpD,const int* __restrict__ lsD,
                        const float* __restrict__ g32,const float* __restrict__ eg32,
                        float* __restrict__ outF){
  int a=blockIdx.x*blockDim.x+threadIdx.x;
  if(a>=N_ATOMS) return;
  int sb=rpS[a], se=rpS[a+1], db=rpD[a], de_=rpD[a+1];
  float s1x=0.f,s1y=0.f,s1z=0.f;
  for(int j=sb;j<se;j++){ int e=lsS[j]; s1x+=g32[(size_t)e*3]; s1y+=g32[(size_t)e*3+1]; s1z+=g32[(size_t)e*3+2]; }
  float s2x=0.f,s2y=0.f,s2z=0.f;
  for(int j=db;j<de_;j++){ int e=lsD[j]; s2x-=g32[(size_t)e*3]; s2y-=g32[(size_t)e*3+1]; s2z-=g32[(size_t)e*3+2]; }
  float apx=s1x+s2x, apy=s1y+s2y, apz=s1z+s2z;
  float Sx=0.f,Sy=0.f,Sz=0.f;
  for(int j=sb;j<se;j++){ int e=lsS[j]; Sx+=eg32[(size_t)e*3]; Sy+=eg32[(size_t)e*3+1]; Sz+=eg32[(size_t)e*3+2]; }
  for(int j=db;j<de_;j++){ int e=lsD[j]; Sx-=eg32[(size_t)e*3]; Sy-=eg32[(size_t)e*3+1]; Sz-=eg32[(size_t)e*3+2]; }
  outF[3*a  ]=-(apx+Sx);
  outF[3*a+1]=-(apy+Sy);
  outF[3*a+2]=-(apz+Sz);
}

extern "C" void kernel_launch(void* const* d_in, const int* in_sizes, int n_in,
                              void* d_out, int out_size)
{
  const float* atom_pos=(const float*)d_in[0];
  const float* edge_attr=(const float*)d_in[1];
  const float* eagrad=(const float*)d_in[2];
  const float* W_mat=(const float*)d_in[3];
  const float* b_mat=(const float*)d_in[4];
  const float* W_emb=(const float*)d_in[5];
  const float* b_emb=(const float*)d_in[6];
  const float* Wv=(const float*)d_in[7];
  const float* Wr=(const float*)d_in[8];
  const float* Wx=(const float*)d_in[9];
  const float* w_out=(const float*)d_in[10];
  const int* edge_index=(const int*)d_in[11];
  const int* neo=(const int*)d_in[12];
  const int* batch=(const int*)d_in[13];
  float* out=(float*)d_out;
  const int* src=edge_index;
  const int* dst=edge_index+E_EDGES;
  const int E=E_EDGES;

  void* basev=nullptr;
  cudaGetSymbolAddress(&basev, g_scratch);
  float* bf=(float*)basev;
  size_t o=0;
  auto F=[&](size_t n){ float* p=bf+o; o+=n; return p; };
  float* pre1=F(EH); float* spre=F(EH);
  float* x0=F(EH); float* x1=F(EH); float* x2=F(EH); float* x3=F(EH);
  float* gpre0=F(EH); float* gpre1=F(EH); float* gpre2=F(EH);
  float* z0=F(EH); float* z1=F(EH); float* z2=F(EH);
  float* t1=F(EH); float* t2=F(EH); float* t3=F(EH);
  float* de=F((size_t)E*169);
  float* rbf=F((size_t)E*20);
  float* drbf0=F((size_t)E*20); float* drbf1=F((size_t)E*20); float* drbf2=F((size_t)E*20);
  float* l1l2=F((size_t)E*8);
  float* dbuf=F(E); float* envb=F(E);
  float* g32=F((size_t)E*3); float* eg32=F((size_t)E*3);
  float* WvR=F(1024); float* WembT=F(16384); float* WmatT=F(21632);
  float* WxT=F(3*16384); float* WrT=F(3*2560);
  o=(o+1)&~(size_t)1;
  double* denvD=(double*)(bf+o); o+=2*(size_t)E;
  double* dlD=(double*)(bf+o); o+=2*(size_t)E*8;
  int* bi=(int*)(bf+o);
  size_t oi=0;
  auto I=[&](size_t n){ int* p=bi+oi; oi+=n; return p; };
  int* rp_dst=I(E+1); int* rp_src=I(E+1);
  int* cur_dst=I(E); int* cur_src=I(E);
  int* csr_dst=I(LE_EDGES); int* csr_src=I(LE_EDGES);
  int* rpAS=I(N_ATOMS+1); int* rpAD=I(N_ATOMS+1);
  int* curAS=I(N_ATOMS); int* curAD=I(N_ATOMS);
  int* lsAS=I(E); int* lsAD=I(E);

  float* dx=x3;
  float* xs[4]={x0,x1,x2,x3};
  float* gpres[3]={gpre0,gpre1,gpre2};
  float* zs[3]={z0,z1,z2};
  float* drbfs[3]={drbf0,drbf1,drbf2};

  dim3 gN1(E/64,1), gN2(E/64,2);

  // ---- launch indices 0..7: prep, geom, then GEMMs (ncu -s 5 lands on x0 GEMM)
  prep_all_k<<<375,256>>>(Wv,WvR,W_emb,WembT,W_mat,WmatT,Wx,WxT,Wr,WrT);          // 0
  geom_fwd_k<<<E/256,256>>>(atom_pos,src,dst,dbuf,envb,rbf,l1l2);                 // 1
  gemm_k<0,0><<<gN1,256>>>(l1l2,nullptr,nullptr,WvR,nullptr,nullptr,spre,nullptr,E,128,8);   // 2
  gemm_k<0,0><<<gN1,256>>>(rbf,nullptr,nullptr,Wr,nullptr,nullptr,gpre0,nullptr,E,128,20);   // 3
  gemm_k<2,0><<<gN1,256>>>(edge_attr,nullptr,envb,W_mat,b_mat,nullptr,pre1,nullptr,E,128,169); // 4
  gemm_k<1,7><<<gN1,256>>>(pre1,nullptr,nullptr,W_emb,b_emb,spre,x0,nullptr,E,128,128);      // 5 <- capture
  gemm_k<0,0><<<gN1,256>>>(rbf,nullptr,nullptr,Wr+2560,nullptr,nullptr,gpre1,nullptr,E,128,20); // 6
  gemm_k<0,0><<<gN1,256>>>(rbf,nullptr,nullptr,Wr+5120,nullptr,nullptr,gpre2,nullptr,E,128,20); // 7

  // ---- CSR builds + memsets
  cudaMemsetAsync(out,0,(size_t)out_size*sizeof(float));
  cudaMemsetAsync(cur_dst,0,(size_t)E*sizeof(int));
  cudaMemsetAsync(cur_src,0,(size_t)E*sizeof(int));
  cudaMemsetAsync(curAS,0,(size_t)N_ATOMS*sizeof(int));
  cudaMemsetAsync(curAD,0,(size_t)N_ATOMS*sizeof(int));

  hist_k<<<LE_EDGES/256,256>>>(neo,cur_src,cur_dst);
  scan_k<<<1,1024>>>(cur_dst,rp_dst,E);
  scan_k<<<1,1024>>>(cur_src,rp_src,E);
  cudaMemcpyAsync(cur_dst,rp_dst,(size_t)E*sizeof(int),cudaMemcpyDeviceToDevice);
  cudaMemcpyAsync(cur_src,rp_src,(size_t)E*sizeof(int),cudaMemcpyDeviceToDevice);
  fill_k<<<LE_EDGES/256,256>>>(neo,cur_src,cur_dst,csr_src,csr_dst);

  hist_atom_k<<<E/256,256>>>(src,dst,curAS,curAD);
  scan_k<<<1,1024>>>(curAS,rpAS,N_ATOMS);
  scan_k<<<1,1024>>>(curAD,rpAD,N_ATOMS);
  cudaMemcpyAsync(curAS,rpAS,(size_t)N_ATOMS*sizeof(int),cudaMemcpyDeviceToDevice);
  cudaMemcpyAsync(curAD,rpAD,(size_t)N_ATOMS*sizeof(int),cudaMemcpyDeviceToDevice);
  fill_atom_k<<<E/256,256>>>(src,dst,curAS,curAD,lsAS,lsAD);
  sort_atom_k<<<(N_ATOMS+255)/256,256>>>(rpAS,lsAS);
  sort_atom_k<<<(N_ATOMS+255)/256,256>>>(rpAD,lsAD);

  // ---- conv layers
  for(int l=0;l<3;l++){
    fwd_xg_k<<<EH/1024,256>>>((const float4*)xs[l],(const float4*)gpres[l],(float4*)t1);
    csr_gather_k<<<E*32/256,256>>>(rp_dst,csr_dst,t1,t2);
    gemm_k<0,3><<<gN1,256>>>(t2,nullptr,nullptr,Wx+(size_t)l*16384,nullptr,xs[l],zs[l],xs[l+1],E,128,128);
  }
  energy_k<<<E*32/256,256>>>(x3,envb,w_out,src,batch,denvD,out);

  // ---- backward
  b1b_k<<<EH/1024,256>>>(envb,w_out,dx);
  for(int l=2;l>=0;l--){
    gemm_k<3,0><<<gN1,256>>>(dx,zs[l],nullptr,WxT+(size_t)l*16384,nullptr,nullptr,t1,nullptr,E,128,128);
    csr_gather_k<<<E*32/256,256>>>(rp_src,csr_src,t1,t2);
    b5_k<<<EH/1024,256>>>((const float4*)t2,(const float4*)xs[l],(const float4*)gpres[l],(float4*)dx,(float4*)t3);
    gemm_k<0,0><<<gN1,256>>>(t3,nullptr,nullptr,WrT+(size_t)l*2560,nullptr,nullptr,drbfs[l],nullptr,E,20,128);
  }
  b8_k<<<E*32/256,256>>>(dx,spre,WvR,dlD);
  gemm_k<0,0><<<gN1,256>>>(dx,nullptr,nullptr,WembT,nullptr,nullptr,t1,nullptr,E,128,128);
  gemm_k<3,0><<<gN2,256>>>(t1,pre1,nullptr,WmatT,nullptr,nullptr,de,nullptr,E,169,128);
  b7b_k<<<E*32/256,256>>>(de,edge_attr,eagrad,envb,denvD,eg32);
  edge_grad_k<<<E/256,256>>>(dbuf,denvD,drbf0,drbf1,drbf2,dlD,l1l2,g32);
  force_k<<<(N_ATOMS+255)/256,256>>>(rpAS,lsAS,rpAD,lsAD,g32,eg32,out+NGRAPH);
}